// round 4
// baseline (speedup 1.0000x reference)
#include <cuda_runtime.h>

#define NUM_NODES 500000
#define D 128
#define U 32
#define T 4
#define A 32
#define N_SRC 65536
#define B 8192
#define E 262144
#define BB 32      // batch rows per finalize block
#define NBINS (T * B)   // 32768 (t, dst) bins

// Scratch (device globals; no allocation)
__device__ float g_agg[B * T * U];   // agg[b][t][u], 4 MB
__device__ int   g_cnt[NBINS];       // per-bin edge count
__device__ int   g_off[NBINS];       // CSR start offsets (stable)
__device__ int   g_cur[NBINS];       // scatter cursors (mutated)
__device__ int   g_eidx[T * E];      // CSR payload: row id = node*T + t

// ---------------------------------------------------------------------------
// K1: zero bin counters (32768 ints)
// ---------------------------------------------------------------------------
__global__ void zero_cnt_kernel() {
    int i = blockIdx.x * blockDim.x + threadIdx.x;
    ((int4*)g_cnt)[i] = make_int4(0, 0, 0, 0);
}

// ---------------------------------------------------------------------------
// K2: histogram edges into (t, dst) bins
// ---------------------------------------------------------------------------
__global__ void hist_kernel(const int* __restrict__ edge_dst) {
    const int t = blockIdx.y;
    const int e = blockIdx.x * blockDim.x + threadIdx.x;
    const int dst = __ldg(&edge_dst[t * E + e]);
    atomicAdd(&g_cnt[t * B + dst], 1);
}

// ---------------------------------------------------------------------------
// K3: exclusive scan of 32768 bin counts (single block, 1024 threads, 32/thread)
// ---------------------------------------------------------------------------
__global__ __launch_bounds__(1024) void scan_kernel() {
    const int tid  = threadIdx.x;
    const int lane = tid & 31;
    const int warp = tid >> 5;

    int local[32];
    int s = 0;
    #pragma unroll
    for (int i = 0; i < 32; i++) { local[i] = s; s += g_cnt[tid * 32 + i]; }

    // inclusive warp scan of per-thread sums
    int v = s;
    #pragma unroll
    for (int o = 1; o < 32; o <<= 1) {
        int n = __shfl_up_sync(0xFFFFFFFFu, v, o);
        if (lane >= o) v += n;
    }
    __shared__ int wsum[32];
    if (lane == 31) wsum[warp] = v;
    __syncthreads();
    if (warp == 0) {
        int w = wsum[lane];
        #pragma unroll
        for (int o = 1; o < 32; o <<= 1) {
            int n = __shfl_up_sync(0xFFFFFFFFu, w, o);
            if (lane >= o) w += n;
        }
        wsum[lane] = w;
    }
    __syncthreads();

    const int excl = v - s + (warp ? wsum[warp - 1] : 0);
    #pragma unroll
    for (int i = 0; i < 32; i++) {
        const int o = excl + local[i];
        g_off[tid * 32 + i] = o;
        g_cur[tid * 32 + i] = o;
    }
}

// ---------------------------------------------------------------------------
// K4: scatter edges into CSR order; payload = resolved nte row (node*T + t)
// ---------------------------------------------------------------------------
__global__ void scatter_kernel(const int* __restrict__ input_nodes,
                               const int* __restrict__ edge_src,
                               const int* __restrict__ edge_dst) {
    const int t = blockIdx.y;
    const int e = blockIdx.x * blockDim.x + threadIdx.x;
    const int src  = __ldg(&edge_src[t * E + e]);
    const int dst  = __ldg(&edge_dst[t * E + e]);
    const int node = __ldg(&input_nodes[src]);
    const int pos  = atomicAdd(&g_cur[t * B + dst], 1);
    g_eidx[pos] = node * T + t;
}

// ---------------------------------------------------------------------------
// K5: pull aggregation. One warp per (t, dst) bin.
// 4 edges in flight; 8 lanes per edge each read one float4 (one 128 B line
// per 8-lane group). Cross-group shuffle-reduce, one coalesced 128 B store.
// Writes every agg row -> replaces the zero pass.
// ---------------------------------------------------------------------------
__global__ __launch_bounds__(256) void pull_kernel(const float* __restrict__ nte_tab) {
    const int bin  = blockIdx.x * 8 + (threadIdx.x >> 5);   // 0..NBINS-1
    const int lane = threadIdx.x & 31;
    const int t    = bin >> 13;          // bin = t*B + dst, B = 8192
    const int dst  = bin & (B - 1);

    const int start = __ldg(&g_off[bin]);
    const int cnt   = __ldg(&g_cnt[bin]);

    const int sub = lane & 7;            // float4 slot within row
    const int grp = lane >> 3;           // edge subgroup 0..3

    float4 acc = make_float4(0.f, 0.f, 0.f, 0.f);
    for (int base = 0; base < cnt; base += 4) {
        const int e = base + grp;
        if (e < cnt) {
            const int row = __ldg(&g_eidx[start + e]);
            const float4 v = __ldg((const float4*)nte_tab + (size_t)row * (U / 4) + sub);
            acc.x += v.x; acc.y += v.y; acc.z += v.z; acc.w += v.w;
        }
    }
    // reduce the 4 edge subgroups (xor 8, then 16)
    #pragma unroll
    for (int o = 8; o <= 16; o <<= 1) {
        acc.x += __shfl_xor_sync(0xFFFFFFFFu, acc.x, o);
        acc.y += __shfl_xor_sync(0xFFFFFFFFu, acc.y, o);
        acc.z += __shfl_xor_sync(0xFFFFFFFFu, acc.z, o);
        acc.w += __shfl_xor_sync(0xFFFFFFFFu, acc.w, o);
    }
    if (lane < 8)
        ((float4*)g_agg)[((size_t)dst * T + t) * (U / 4) + lane] = acc;
}

// ---------------------------------------------------------------------------
// K6: attention + combine + trans GEMM + residual + L2-normalize (unchanged)
// ---------------------------------------------------------------------------
__global__ __launch_bounds__(256) void finalize_kernel(
    const float* __restrict__ node_emb,     // [NUM_NODES][D]
    const float* __restrict__ w,            // [T][U][D]
    const float* __restrict__ ws1,          // [T][U][A]
    const float* __restrict__ ws2,          // [T][A]
    const int*  __restrict__ out_nodes,     // [B]
    float*      __restrict__ out)           // [B][T][D]
{
    __shared__ float nte_s[BB][T * U];
    __shared__ float scores_s[BB][T];
    __shared__ float att_s[BB][T];
    __shared__ float comb_s[BB][U];

    const int b0   = blockIdx.x * BB;
    const int tid  = threadIdx.x;
    const int lane = tid & 31;
    const int warp = tid >> 5;
    const int t    = warp & 3;
    const int half = warp >> 2;
    const int bbase = half * 16;

    float w1r[U];
    #pragma unroll
    for (int u = 0; u < U; u++) w1r[u] = __ldg(&ws1[(t * U + u) * A + lane]);
    const float w2r = __ldg(&ws2[t * A + lane]);

    {
        const float4* s4 = (const float4*)(g_agg + (size_t)b0 * T * U);
        float4* d4 = (float4*)&nte_s[0][0];
        #pragma unroll
        for (int i = tid; i < BB * T * U / 4; i += 256) d4[i] = s4[i];
    }
    __syncthreads();

    #pragma unroll
    for (int i = 0; i < 16; i++) {
        const int bb = bbase + i;
        float acc = 0.f;
        #pragma unroll
        for (int u = 0; u < U; u++) acc += nte_s[bb][t * U + u] * w1r[u];
        float sc = tanhf(acc) * w2r;
        #pragma unroll
        for (int o = 16; o; o >>= 1) sc += __shfl_xor_sync(0xFFFFFFFFu, sc, o);
        if (lane == 0) scores_s[bb][t] = sc;
    }
    __syncthreads();

    if (tid < BB) {
        float s0 = scores_s[tid][0], s1 = scores_s[tid][1];
        float s2 = scores_s[tid][2], s3 = scores_s[tid][3];
        float m = fmaxf(fmaxf(s0, s1), fmaxf(s2, s3));
        float e0 = __expf(s0 - m), e1 = __expf(s1 - m);
        float e2 = __expf(s2 - m), e3 = __expf(s3 - m);
        float inv = 1.f / (e0 + e1 + e2 + e3);
        att_s[tid][0] = e0 * inv; att_s[tid][1] = e1 * inv;
        att_s[tid][2] = e2 * inv; att_s[tid][3] = e3 * inv;
    }
    __syncthreads();

    #pragma unroll
    for (int i = tid; i < BB * U; i += 256) {
        const int bb = i >> 5, u = i & 31;
        float c = 0.f;
        #pragma unroll
        for (int tt = 0; tt < T; tt++) c += att_s[bb][tt] * nte_s[bb][tt * U + u];
        comb_s[bb][u] = c;
    }
    __syncthreads();

    float4 acc[16];
    #pragma unroll
    for (int i = 0; i < 16; i++) acc[i] = make_float4(0.f, 0.f, 0.f, 0.f);

    const float4* wbase = (const float4*)w + (size_t)t * U * (D / 4) + lane;
    #pragma unroll
    for (int uc = 0; uc < U; uc += 8) {
        float4 wr[8];
        #pragma unroll
        for (int j = 0; j < 8; j++) wr[j] = __ldg(&wbase[(uc + j) * (D / 4)]);
        #pragma unroll
        for (int i = 0; i < 16; i++) {
            const int bb = bbase + i;
            #pragma unroll
            for (int j = 0; j < 8; j++) {
                const float c = comb_s[bb][uc + j];
                acc[i].x += c * wr[j].x; acc[i].y += c * wr[j].y;
                acc[i].z += c * wr[j].z; acc[i].w += c * wr[j].w;
            }
        }
    }

    #pragma unroll
    for (int i = 0; i < 16; i++) {
        const int bb = bbase + i;
        const int b  = b0 + bb;

        const int nidx = __ldg(&out_nodes[b]);
        const float4 nv = __ldg((const float4*)node_emb + (size_t)nidx * (D / 4) + lane);
        float4 o = acc[i];
        o.x += nv.x; o.y += nv.y; o.z += nv.z; o.w += nv.w;

        float ss = o.x * o.x + o.y * o.y + o.z * o.z + o.w * o.w;
        #pragma unroll
        for (int off = 16; off; off >>= 1) ss += __shfl_xor_sync(0xFFFFFFFFu, ss, off);

        const float scale = 1.f / fmaxf(sqrtf(ss), 1e-12f);
        o.x *= scale; o.y *= scale; o.z *= scale; o.w *= scale;

        ((float4*)out)[(size_t)(b * T + t) * (D / 4) + lane] = o;
    }
}

// ---------------------------------------------------------------------------
// Launch
// ---------------------------------------------------------------------------
extern "C" void kernel_launch(void* const* d_in, const int* in_sizes, int n_in,
                              void* d_out, int out_size) {
    const float* node_emb     = (const float*)d_in[0];  // [500000][128]
    const float* nte_tab      = (const float*)d_in[1];  // [500000][4][32]
    const float* trans_w      = (const float*)d_in[2];  // [4][32][128]
    const float* trans_w_s1   = (const float*)d_in[3];  // [4][32][32]
    const float* trans_w_s2   = (const float*)d_in[4];  // [4][32][1]
    const int*   input_nodes  = (const int*)d_in[5];    // [65536]
    const int*   output_nodes = (const int*)d_in[6];    // [8192]
    const int*   edge_src     = (const int*)d_in[7];    // [4][262144]
    const int*   edge_dst     = (const int*)d_in[8];    // [4][262144]
    float*       out          = (float*)d_out;          // [8192][4][128]

    zero_cnt_kernel<<<NBINS / 4 / 256, 256>>>();

    dim3 grid_h(E / 512, T);
    hist_kernel<<<grid_h, 512>>>(edge_dst);

    scan_kernel<<<1, 1024>>>();

    dim3 grid_s(E / 256, T);
    scatter_kernel<<<grid_s, 256>>>(input_nodes, edge_src, edge_dst);

    pull_kernel<<<NBINS / 8, 256>>>(nte_tab);

    finalize_kernel<<<B / BB, 256>>>(node_emb, trans_w, trans_w_s1, trans_w_s2,
                                     output_nodes, out);
}

// round 5
// speedup vs baseline: 2.3702x; 2.3702x over previous
#include <cuda_runtime.h>

#define NUM_NODES 500000
#define D 128
#define U 32
#define T 4
#define A 32
#define N_SRC 65536
#define B 8192
#define E 262144
#define BB 32  // batch rows per finalize block

// Scratch accumulator: agg[b][t][u]  (B*T*U floats = 4 MB)
__device__ float g_agg[B * T * U];

// ---------------------------------------------------------------------------
// Kernel 1: edge aggregation with vectorized global reductions.
// 8 lanes per edge, 2 edges per thread (independent chains for MLP).
//   agg[edge_dst[t,e], t, :] += node_type_embeddings[input_nodes[edge_src[t,e]], t, :]
// ---------------------------------------------------------------------------
__global__ __launch_bounds__(256) void edge_agg_kernel(
    const float* __restrict__ nte_tab,
    const int* __restrict__ input_nodes,
    const int* __restrict__ edge_src,
    const int* __restrict__ edge_dst) {
    const int t   = blockIdx.y;
    const int e0  = blockIdx.x * 64 + (threadIdx.x >> 3);   // 64 edges / block
    const int e1  = e0 + 32;
    const int sub = threadIdx.x & 7;                        // float4 slot in row

    const int src0 = __ldg(&edge_src[t * E + e0]);
    const int src1 = __ldg(&edge_src[t * E + e1]);
    const int dst0 = __ldg(&edge_dst[t * E + e0]);
    const int dst1 = __ldg(&edge_dst[t * E + e1]);
    const int n0   = __ldg(&input_nodes[src0]);
    const int n1   = __ldg(&input_nodes[src1]);

    const float4 v0 = __ldg((const float4*)nte_tab + (size_t)(n0 * T + t) * (U / 4) + sub);
    const float4 v1 = __ldg((const float4*)nte_tab + (size_t)(n1 * T + t) * (U / 4) + sub);

    float* p0 = g_agg + ((size_t)dst0 * T + t) * U + sub * 4;
    float* p1 = g_agg + ((size_t)dst1 * T + t) * U + sub * 4;
    asm volatile("red.global.add.v4.f32 [%0], {%1,%2,%3,%4};"
                 :: "l"(p0), "f"(v0.x), "f"(v0.y), "f"(v0.z), "f"(v0.w) : "memory");
    asm volatile("red.global.add.v4.f32 [%0], {%1,%2,%3,%4};"
                 :: "l"(p1), "f"(v1.x), "f"(v1.y), "f"(v1.z), "f"(v1.w) : "memory");
}

// ---------------------------------------------------------------------------
// Kernel 2: attention + combine + trans GEMM + residual + L2-normalize.
// One block = BB=32 batch rows, 256 threads (8 warps).
// Warp w owns t = w&3 and batch-half = w>>2; weights live in REGISTERS
// across the 16 batch rows.
// ---------------------------------------------------------------------------
__global__ __launch_bounds__(256) void finalize_kernel(
    const float* __restrict__ node_emb,     // [NUM_NODES][D]
    const float* __restrict__ w,            // [T][U][D]
    const float* __restrict__ ws1,          // [T][U][A]
    const float* __restrict__ ws2,          // [T][A]
    const int*  __restrict__ out_nodes,     // [B]
    float*      __restrict__ out)           // [B][T][D]
{
    __shared__ float nte_s[BB][T * U];
    __shared__ float scores_s[BB][T];
    __shared__ float att_s[BB][T];
    __shared__ float comb_s[BB][U];

    const int b0   = blockIdx.x * BB;
    const int tid  = threadIdx.x;
    const int lane = tid & 31;
    const int warp = tid >> 5;
    const int t    = warp & 3;
    const int half = warp >> 2;
    const int bbase = half * 16;

    float w1r[U];
    #pragma unroll
    for (int u = 0; u < U; u++) w1r[u] = __ldg(&ws1[(t * U + u) * A + lane]);
    const float w2r = __ldg(&ws2[t * A + lane]);

    {
        const float4* s4 = (const float4*)(g_agg + (size_t)b0 * T * U);
        float4* d4 = (float4*)&nte_s[0][0];
        #pragma unroll
        for (int i = tid; i < BB * T * U / 4; i += 256) d4[i] = s4[i];
    }
    __syncthreads();

    #pragma unroll
    for (int i = 0; i < 16; i++) {
        const int bb = bbase + i;
        float acc = 0.f;
        #pragma unroll
        for (int u = 0; u < U; u++) acc += nte_s[bb][t * U + u] * w1r[u];
        float sc = tanhf(acc) * w2r;
        #pragma unroll
        for (int o = 16; o; o >>= 1) sc += __shfl_xor_sync(0xFFFFFFFFu, sc, o);
        if (lane == 0) scores_s[bb][t] = sc;
    }
    __syncthreads();

    if (tid < BB) {
        float s0 = scores_s[tid][0], s1 = scores_s[tid][1];
        float s2 = scores_s[tid][2], s3 = scores_s[tid][3];
        float m = fmaxf(fmaxf(s0, s1), fmaxf(s2, s3));
        float e0 = __expf(s0 - m), e1 = __expf(s1 - m);
        float e2 = __expf(s2 - m), e3 = __expf(s3 - m);
        float inv = 1.f / (e0 + e1 + e2 + e3);
        att_s[tid][0] = e0 * inv; att_s[tid][1] = e1 * inv;
        att_s[tid][2] = e2 * inv; att_s[tid][3] = e3 * inv;
    }
    __syncthreads();

    #pragma unroll
    for (int i = tid; i < BB * U; i += 256) {
        const int bb = i >> 5, u = i & 31;
        float c = 0.f;
        #pragma unroll
        for (int tt = 0; tt < T; tt++) c += att_s[bb][tt] * nte_s[bb][tt * U + u];
        comb_s[bb][u] = c;
    }
    __syncthreads();

    float4 acc[16];
    #pragma unroll
    for (int i = 0; i < 16; i++) acc[i] = make_float4(0.f, 0.f, 0.f, 0.f);

    const float4* wbase = (const float4*)w + (size_t)t * U * (D / 4) + lane;
    #pragma unroll
    for (int uc = 0; uc < U; uc += 8) {
        float4 wr[8];
        #pragma unroll
        for (int j = 0; j < 8; j++) wr[j] = __ldg(&wbase[(uc + j) * (D / 4)]);
        #pragma unroll
        for (int i = 0; i < 16; i++) {
            const int bb = bbase + i;
            #pragma unroll
            for (int j = 0; j < 8; j++) {
                const float c = comb_s[bb][uc + j];
                acc[i].x += c * wr[j].x; acc[i].y += c * wr[j].y;
                acc[i].z += c * wr[j].z; acc[i].w += c * wr[j].w;
            }
        }
    }

    #pragma unroll
    for (int i = 0; i < 16; i++) {
        const int bb = bbase + i;
        const int b  = b0 + bb;

        const int nidx = __ldg(&out_nodes[b]);
        const float4 nv = __ldg((const float4*)node_emb + (size_t)nidx * (D / 4) + lane);
        float4 o = acc[i];
        o.x += nv.x; o.y += nv.y; o.z += nv.z; o.w += nv.w;

        float ss = o.x * o.x + o.y * o.y + o.z * o.z + o.w * o.w;
        #pragma unroll
        for (int off = 16; off; off >>= 1) ss += __shfl_xor_sync(0xFFFFFFFFu, ss, off);

        const float scale = 1.f / fmaxf(sqrtf(ss), 1e-12f);
        o.x *= scale; o.y *= scale; o.z *= scale; o.w *= scale;

        ((float4*)out)[(size_t)(b * T + t) * (D / 4) + lane] = o;
    }
}

// ---------------------------------------------------------------------------
// Launch
// ---------------------------------------------------------------------------
extern "C" void kernel_launch(void* const* d_in, const int* in_sizes, int n_in,
                              void* d_out, int out_size) {
    const float* node_emb     = (const float*)d_in[0];  // [500000][128]
    const float* nte_tab      = (const float*)d_in[1];  // [500000][4][32]
    const float* trans_w      = (const float*)d_in[2];  // [4][32][128]
    const float* trans_w_s1   = (const float*)d_in[3];  // [4][32][32]
    const float* trans_w_s2   = (const float*)d_in[4];  // [4][32][1]
    const int*   input_nodes  = (const int*)d_in[5];    // [65536]
    const int*   output_nodes = (const int*)d_in[6];    // [8192]
    const int*   edge_src     = (const int*)d_in[7];    // [4][262144]
    const int*   edge_dst     = (const int*)d_in[8];    // [4][262144]
    float*       out          = (float*)d_out;          // [8192][4][128]

    // Zero accumulator as a graph memset node (faster than a tiny kernel).
    void* agg_ptr = nullptr;
    cudaGetSymbolAddress(&agg_ptr, g_agg);
    cudaMemsetAsync(agg_ptr, 0, (size_t)B * T * U * sizeof(float));

    dim3 grid_e(E / 64, T);
    edge_agg_kernel<<<grid_e, 256>>>(nte_tab, input_nodes, edge_src, edge_dst);

    finalize_kernel<<<B / BB, 256>>>(node_emb, trans_w, trans_w_s1, trans_w_s2,
                                     output_nodes, out);
}

// round 6
// speedup vs baseline: 2.4613x; 1.0384x over previous
#include <cuda_runtime.h>

#define NUM_NODES 500000
#define D 128
#define U 32
#define T 4
#define A 32
#define N_SRC 65536
#define B 8192
#define E 262144
#define BB 16  // batch rows per finalize block

// Scratch accumulator: agg[b][t][u]  (B*T*U floats = 4 MB)
__device__ float g_agg[B * T * U];

// ---------------------------------------------------------------------------
// Kernel 1: edge aggregation with vectorized global reductions.
// 8 lanes per edge, 2 edges per thread (independent chains for MLP).
// ---------------------------------------------------------------------------
__global__ __launch_bounds__(256) void edge_agg_kernel(
    const float* __restrict__ nte_tab,
    const int* __restrict__ input_nodes,
    const int* __restrict__ edge_src,
    const int* __restrict__ edge_dst) {
    const int t   = blockIdx.y;
    const int e0  = blockIdx.x * 64 + (threadIdx.x >> 3);   // 64 edges / block
    const int e1  = e0 + 32;
    const int sub = threadIdx.x & 7;                        // float4 slot in row

    const int src0 = __ldg(&edge_src[t * E + e0]);
    const int src1 = __ldg(&edge_src[t * E + e1]);
    const int dst0 = __ldg(&edge_dst[t * E + e0]);
    const int dst1 = __ldg(&edge_dst[t * E + e1]);
    const int n0   = __ldg(&input_nodes[src0]);
    const int n1   = __ldg(&input_nodes[src1]);

    const float4 v0 = __ldg((const float4*)nte_tab + (size_t)(n0 * T + t) * (U / 4) + sub);
    const float4 v1 = __ldg((const float4*)nte_tab + (size_t)(n1 * T + t) * (U / 4) + sub);

    float* p0 = g_agg + ((size_t)dst0 * T + t) * U + sub * 4;
    float* p1 = g_agg + ((size_t)dst1 * T + t) * U + sub * 4;
    asm volatile("red.global.add.v4.f32 [%0], {%1,%2,%3,%4};"
                 :: "l"(p0), "f"(v0.x), "f"(v0.y), "f"(v0.z), "f"(v0.w) : "memory");
    asm volatile("red.global.add.v4.f32 [%0], {%1,%2,%3,%4};"
                 :: "l"(p1), "f"(v1.x), "f"(v1.y), "f"(v1.z), "f"(v1.w) : "memory");
}

// ---------------------------------------------------------------------------
// Kernel 2: attention + combine + trans GEMM + residual + L2-normalize.
// One block = BB=16 batch rows, 256 threads (8 warps).
// Warp w owns t = w&3, half = w>>2 -> 8 batch rows. acc[8] + wr[4] keeps
// register pressure <=64 so 4 blocks/SM (50% occ), grid = 512 blocks.
// ---------------------------------------------------------------------------
__global__ __launch_bounds__(256, 4) void finalize_kernel(
    const float* __restrict__ node_emb,     // [NUM_NODES][D]
    const float* __restrict__ w,            // [T][U][D]
    const float* __restrict__ ws1,          // [T][U][A]
    const float* __restrict__ ws2,          // [T][A]
    const int*  __restrict__ out_nodes,     // [B]
    float*      __restrict__ out)           // [B][T][D]
{
    __shared__ float nte_s[BB][T * U];      // 8 KB
    __shared__ float scores_s[BB][T];
    __shared__ float att_s[BB][T];
    __shared__ float comb_s[BB][U];         // 2 KB

    const int b0   = blockIdx.x * BB;
    const int tid  = threadIdx.x;
    const int lane = tid & 31;
    const int warp = tid >> 5;
    const int t    = warp & 3;
    const int bbase = (warp >> 2) * 8;      // 8 rows per warp

    // Load nte for BB rows (contiguous 8 KB, float4)
    {
        const float4* s4 = (const float4*)(g_agg + (size_t)b0 * T * U);
        float4* d4 = (float4*)&nte_s[0][0];
        #pragma unroll
        for (int i = tid; i < BB * T * U / 4; i += 256) d4[i] = s4[i];
    }
    __syncthreads();

    // Stage A: score[bb][t] = sum_a tanh(sum_u nte*ws1)[a] * ws2[a]
    // ws1 column cached in regs (reused across 8 rows; dead before stage B).
    {
        float w1r[U];
        #pragma unroll
        for (int u = 0; u < U; u++) w1r[u] = __ldg(&ws1[(t * U + u) * A + lane]);
        const float w2r = __ldg(&ws2[t * A + lane]);

        #pragma unroll
        for (int i = 0; i < 8; i++) {
            const int bb = bbase + i;
            float acc = 0.f;
            #pragma unroll
            for (int u = 0; u < U; u++) acc += nte_s[bb][t * U + u] * w1r[u];
            float sc = tanhf(acc) * w2r;
            #pragma unroll
            for (int o = 16; o; o >>= 1) sc += __shfl_xor_sync(0xFFFFFFFFu, sc, o);
            if (lane == 0) scores_s[bb][t] = sc;
        }
    }
    __syncthreads();

    // Softmax over T=4 (one thread per batch row)
    if (tid < BB) {
        float s0 = scores_s[tid][0], s1 = scores_s[tid][1];
        float s2 = scores_s[tid][2], s3 = scores_s[tid][3];
        float m = fmaxf(fmaxf(s0, s1), fmaxf(s2, s3));
        float e0 = __expf(s0 - m), e1 = __expf(s1 - m);
        float e2 = __expf(s2 - m), e3 = __expf(s3 - m);
        float inv = 1.f / (e0 + e1 + e2 + e3);
        att_s[tid][0] = e0 * inv; att_s[tid][1] = e1 * inv;
        att_s[tid][2] = e2 * inv; att_s[tid][3] = e3 * inv;
    }
    __syncthreads();

    // combined[bb][u] = sum_t att[bb][t] * nte[bb][t][u]  (BB*U = 512 items)
    #pragma unroll
    for (int i = tid; i < BB * U; i += 256) {
        const int bb = i >> 5, u = i & 31;
        float c = 0.f;
        #pragma unroll
        for (int tt = 0; tt < T; tt++) c += att_s[bb][tt] * nte_s[bb][tt * U + u];
        comb_s[bb][u] = c;
    }
    __syncthreads();

    // Stage B: out[b,t,:] = normalize(node_emb[out_nodes[b],:] + combined[b] @ w[t])
    // lane owns one float4 slice of D; 8-row accumulators, 4-row weight chunks.
    float4 acc[8];
    #pragma unroll
    for (int i = 0; i < 8; i++) acc[i] = make_float4(0.f, 0.f, 0.f, 0.f);

    const float4* wbase = (const float4*)w + (size_t)t * U * (D / 4) + lane;
    #pragma unroll
    for (int uc = 0; uc < U; uc += 4) {
        float4 wr[4];
        #pragma unroll
        for (int j = 0; j < 4; j++) wr[j] = __ldg(&wbase[(uc + j) * (D / 4)]);
        #pragma unroll
        for (int i = 0; i < 8; i++) {
            const int bb = bbase + i;
            #pragma unroll
            for (int j = 0; j < 4; j++) {
                const float c = comb_s[bb][uc + j];
                acc[i].x += c * wr[j].x; acc[i].y += c * wr[j].y;
                acc[i].z += c * wr[j].z; acc[i].w += c * wr[j].w;
            }
        }
    }

    #pragma unroll
    for (int i = 0; i < 8; i++) {
        const int bb = bbase + i;
        const int b  = b0 + bb;

        const int nidx = __ldg(&out_nodes[b]);
        const float4 nv = __ldg((const float4*)node_emb + (size_t)nidx * (D / 4) + lane);
        float4 o = acc[i];
        o.x += nv.x; o.y += nv.y; o.z += nv.z; o.w += nv.w;

        float ss = o.x * o.x + o.y * o.y + o.z * o.z + o.w * o.w;
        #pragma unroll
        for (int off = 16; off; off >>= 1) ss += __shfl_xor_sync(0xFFFFFFFFu, ss, off);

        const float scale = 1.f / fmaxf(sqrtf(ss), 1e-12f);
        o.x *= scale; o.y *= scale; o.z *= scale; o.w *= scale;

        ((float4*)out)[(size_t)(b * T + t) * (D / 4) + lane] = o;
    }
}

// ---------------------------------------------------------------------------
// Launch
// ---------------------------------------------------------------------------
extern "C" void kernel_launch(void* const* d_in, const int* in_sizes, int n_in,
                              void* d_out, int out_size) {
    const float* node_emb     = (const float*)d_in[0];  // [500000][128]
    const float* nte_tab      = (const float*)d_in[1];  // [500000][4][32]
    const float* trans_w      = (const float*)d_in[2];  // [4][32][128]
    const float* trans_w_s1   = (const float*)d_in[3];  // [4][32][32]
    const float* trans_w_s2   = (const float*)d_in[4];  // [4][32][1]
    const int*   input_nodes  = (const int*)d_in[5];    // [65536]
    const int*   output_nodes = (const int*)d_in[6];    // [8192]
    const int*   edge_src     = (const int*)d_in[7];    // [4][262144]
    const int*   edge_dst     = (const int*)d_in[8];    // [4][262144]
    float*       out          = (float*)d_out;          // [8192][4][128]

    // Zero accumulator as a graph memset node.
    void* agg_ptr = nullptr;
    cudaGetSymbolAddress(&agg_ptr, g_agg);
    cudaMemsetAsync(agg_ptr, 0, (size_t)B * T * U * sizeof(float));

    dim3 grid_e(E / 64, T);
    edge_agg_kernel<<<grid_e, 256>>>(nte_tab, input_nodes, edge_src, edge_dst);

    finalize_kernel<<<B / BB, 256>>>(node_emb, trans_w, trans_w_s1, trans_w_s2,
                                     output_nodes, out);
}